// round 4
// baseline (speedup 1.0000x reference)
#include <cuda_runtime.h>
#include <math.h>

#define MDIM 512
#define LDIM 31
#define CTOT 542                 // MDIM + LDIM - 1
#define NX   1024
#define ROWE (NX * LDIM)         // 31744 floats per input row strip
#define XCE  (MDIM * LDIM)       // 15872 floats per output row strip

#define WC     32                // output columns per tile
#define NTILE  (MDIM / WC)       // 16
#define SROW_N (66 * LDIM)       // staged row-combined window: 66 cols x 31
#define TILE_E (WC * LDIM)       // 992

// Static scratch (no runtime allocation allowed)
__device__ float g_yn[MDIM * CTOT];
__device__ float g_rmax1[MDIM];  // per-row max of yn (pre-normalization)
__device__ float g_rmax2[MDIM];  // per-row max of X2 (pre-normalization)

// Deterministic block max (blockDim.x = 512 = 16 warps).
__device__ __forceinline__ float blockReduceMax(float v, float* sred) {
    __syncthreads();                       // protect sred reuse across calls
    int lane = threadIdx.x & 31, wid = threadIdx.x >> 5;
    #pragma unroll
    for (int o = 16; o; o >>= 1) v = fmaxf(v, __shfl_xor_sync(0xffffffffu, v, o));
    if (lane == 0) sred[wid] = v;
    __syncthreads();
    if (wid == 0) {
        float x = (lane < (int)(blockDim.x >> 5)) ? sred[lane] : -INFINITY;
        #pragma unroll
        for (int o = 16; o; o >>= 1) x = fmaxf(x, __shfl_xor_sync(0xffffffffu, x, o));
        if (lane == 0) sred[0] = x;
    }
    __syncthreads();
    return sred[0];
}

// Column resize (antialiased bilinear 0.5x along axis-2) for output col c,
// lambda index l, reading the row-combined window sRow (window starts at
// input col 2*c0-1; interior taps live at local cols 2*dc .. 2*dc+3).
__device__ __forceinline__ float colResize(const float* __restrict__ sRow,
                                           int c, int dc, int l) {
    if (c == 0)
        return (3.f/7.f)*sRow[31 + l] + (3.f/7.f)*sRow[62 + l] + (1.f/7.f)*sRow[93 + l];
    if (c == MDIM - 1)
        return (1.f/7.f)*sRow[62*LDIM + l] + (3.f/7.f)*sRow[63*LDIM + l]
             + (3.f/7.f)*sRow[64*LDIM + l];
    int b = 2 * dc * LDIM + l;
    return 0.125f*sRow[b] + 0.375f*sRow[b + LDIM]
         + 0.375f*sRow[b + 2*LDIM] + 0.125f*sRow[b + 3*LDIM];
}

// ---------------------------------------------------------------------------
// Forward: one block per output row r; 16 column tiles of 32 output cols.
// Fuses antialiased 2x bilinear downscale (rows+cols), lambda-conv [1/4,1/2,1/4],
// H multiply, skewed yn sum, per-row max. ~15KB SMEM -> fully resident grid.
// ---------------------------------------------------------------------------
__global__ void __launch_bounds__(512) k_fwd(const float* __restrict__ X,
                                             const float* __restrict__ H) {
    __shared__ float sRow[SROW_N];   // row-combined input window (66 cols x 31)
    __shared__ float sP[TILE_E];     // H * lambda-conv tile
    __shared__ float syn[CTOT];      // yn accumulator for this row
    __shared__ float sred[32];

    const int r = blockIdx.x, tid = threadIdx.x;

    // Row-resize taps ([1/8,3/8,3/8,1/8], renormalized at edges)
    float w0, w1, w2, w3; int i0, i1, i2, i3;
    if (r == 0) {
        w0 = 0.f;     w1 = 3.f/7.f; w2 = 3.f/7.f; w3 = 1.f/7.f;
        i0 = 0; i1 = 0; i2 = 1; i3 = 2;
    } else if (r == MDIM - 1) {
        w0 = 1.f/7.f; w1 = 3.f/7.f; w2 = 3.f/7.f; w3 = 0.f;
        i0 = 2*r - 1; i1 = 2*r; i2 = 2*r + 1; i3 = i2;
    } else {
        w0 = 0.125f;  w1 = 0.375f;  w2 = 0.375f;  w3 = 0.125f;
        i0 = 2*r - 1; i1 = 2*r; i2 = 2*r + 1; i3 = 2*r + 2;
    }
    const float* X0 = X + (size_t)i0 * ROWE;
    const float* X1 = X + (size_t)i1 * ROWE;
    const float* X2p = X + (size_t)i2 * ROWE;
    const float* X3 = X + (size_t)i3 * ROWE;
    const float* Hr = H + (size_t)r * XCE;

    for (int cc = tid; cc < CTOT; cc += 512) syn[cc] = 0.f;

    for (int t = 0; t < NTILE; ++t) {
        const int c0 = t * WC;
        const int gb = (2 * c0 - 1) * LDIM;   // window start offset (may be -31)

        // Phase A: row-combine 4 input rows over the window (coalesced streams).
        // Out-of-range entries left stale; index math below never reads them.
        __syncthreads();                 // prior-tile sP/syn consumers done
        for (int idx = tid; idx < SROW_N; idx += 512) {
            int g = gb + idx;
            if (g >= 0 && g < ROWE) {
                sRow[idx] = w0 * __ldg(X0 + g) + w1 * __ldg(X1 + g)
                          + w2 * __ldg(X2p + g) + w3 * __ldg(X3 + g);
            }
        }
        __syncthreads();

        // Phase B+C fused: col-resize (recomputed for l-1,l,l+1 in registers),
        // lambda conv [1/4,1/2,1/4] along L (zero pad), multiply by H.
        for (int e = tid; e < TILE_E; e += 512) {
            int dc = e / LDIM, l = e - dc * LDIM;
            int c = c0 + dc;
            float v = 0.5f * colResize(sRow, c, dc, l);
            if (l > 0)        v += 0.25f * colResize(sRow, c, dc, l - 1);
            if (l < LDIM - 1) v += 0.25f * colResize(sRow, c, dc, l + 1);
            sP[e] = __ldg(Hr + c0 * LDIM + e) * v;
        }
        __syncthreads();

        // Phase D: skewed sum into yn accumulator (tile-private range, no races)
        if (tid < WC + LDIM - 1) {                // 62 output positions
            int lcc = tid;
            int ilo = lcc - (WC - 1); if (ilo < 0) ilo = 0;
            int ihi = (lcc < LDIM - 1) ? lcc : (LDIM - 1);
            float acc = 0.f;
            for (int i = ilo; i <= ihi; ++i)
                acc += sP[(lcc - i) * LDIM + i];
            syn[c0 + lcc] += acc;
        }
    }
    __syncthreads();

    // Row max + write yn row
    float lmax = -INFINITY;
    float* ynr = g_yn + r * CTOT;
    for (int cc = tid; cc < CTOT; cc += 512) {
        float v = syn[cc];
        ynr[cc] = v;
        lmax = fmaxf(lmax, v);
    }
    float bm = blockReduceMax(lmax, sred);
    if (tid == 0) g_rmax1[r] = bm;
}

// ---------------------------------------------------------------------------
// Backward pass 1: per-row max of X2 only (H streams once, stays in L2).
// ---------------------------------------------------------------------------
__global__ void __launch_bounds__(512) k_bwd1(const float* __restrict__ y,
                                              const float* __restrict__ H) {
    __shared__ float srr[CTOT];
    __shared__ float sred[32];
    const int r = blockIdx.x, tid = threadIdx.x;

    float v0 = (tid < MDIM) ? g_rmax1[tid] : -INFINITY;
    const float invY = 1.0f / blockReduceMax(v0, sred);

    const float* ynr = g_yn + r * CTOT;
    const float* yr  = y + r * CTOT;
    for (int cc = tid; cc < CTOT; cc += 512)
        srr[cc] = ynr[cc] * invY - yr[cc];
    __syncthreads();

    const float* Hr = H + (size_t)r * XCE;
    float lmax = -INFINITY;
    for (int e = tid; e < XCE; e += 512) {
        int m = e / LDIM, i = e - m * LDIM, c = m + i;
        float v = 0.5f * srr[c];
        if (i > 0)        v += 0.25f * srr[c - 1];
        if (i < LDIM - 1) v += 0.25f * srr[c + 1];
        lmax = fmaxf(lmax, Hr[e] * v);
    }
    float bm = blockReduceMax(lmax, sred);
    if (tid == 0) g_rmax2[r] = bm;
}

// ---------------------------------------------------------------------------
// Backward pass 2: recompute X2 (H L2-resident) and write normalized output.
// ---------------------------------------------------------------------------
__global__ void __launch_bounds__(512) k_bwd2(const float* __restrict__ y,
                                              const float* __restrict__ H,
                                              float* __restrict__ out) {
    __shared__ float srr[CTOT];
    __shared__ float sred[32];
    const int r = blockIdx.x, tid = threadIdx.x;

    float v0 = (tid < MDIM) ? g_rmax1[tid] : -INFINITY;
    const float invY = 1.0f / blockReduceMax(v0, sred);
    float v1 = (tid < MDIM) ? g_rmax2[tid] : -INFINITY;
    const float invO = 1.0f / blockReduceMax(v1, sred);

    const float* ynr = g_yn + r * CTOT;
    const float* yr  = y + r * CTOT;
    for (int cc = tid; cc < CTOT; cc += 512)
        srr[cc] = ynr[cc] * invY - yr[cc];
    __syncthreads();

    const float* Hr   = H   + (size_t)r * XCE;
    float*       outr = out + (size_t)r * XCE;
    for (int e = tid; e < XCE; e += 512) {
        int m = e / LDIM, i = e - m * LDIM, c = m + i;
        float v = 0.5f * srr[c];
        if (i > 0)        v += 0.25f * srr[c - 1];
        if (i < LDIM - 1) v += 0.25f * srr[c + 1];
        outr[e] = (Hr[e] * v) * invO;
    }
}

extern "C" void kernel_launch(void* const* d_in, const int* in_sizes, int n_in,
                              void* d_out, int out_size) {
    // Identify inputs by element count; fall back to metadata order.
    const float *X = 0, *y = 0, *H = 0;
    for (int i = 0; i < n_in; ++i) {
        if      (in_sizes[i] == NX * NX * LDIM)     X = (const float*)d_in[i];
        else if (in_sizes[i] == MDIM * CTOT)        y = (const float*)d_in[i];
        else if (in_sizes[i] == MDIM * MDIM * LDIM) H = (const float*)d_in[i];
    }
    if (!X || !y || !H) {
        X = (const float*)d_in[0];
        y = (const float*)d_in[1];
        H = (const float*)d_in[2];
    }
    float* out = (float*)d_out;

    k_fwd <<<MDIM, 512>>>(X, H);
    k_bwd1<<<MDIM, 512>>>(y, H);
    k_bwd2<<<MDIM, 512>>>(y, H, out);
}